// round 8
// baseline (speedup 1.0000x reference)
#include <cuda_runtime.h>
#include <cuda_bf16.h>
#include <math.h>

#define EMB 128
#define NHEAD 8
#define DHEAD 16
#define KNBR 32
#define NMAX 2048

typedef unsigned long long u64;

// Scratch (no cudaMalloc allowed)
__device__ float4 g_cent[NMAX];
__device__ float  g_qkv [NMAX * 3 * EMB];
__device__ float  g_o   [NMAX * EMB];

__device__ __forceinline__ float dot4(float4 a, float4 b) {
    return a.x*b.x + a.y*b.y + a.z*b.z + a.w*b.w;
}

// Packed fp32 FMA: d.lo = a.lo*b.lo + c.lo ; d.hi = a.hi*b.hi + c.hi
__device__ __forceinline__ u64 ffma2(u64 a, u64 b, u64 c) {
    u64 d;
    asm("fma.rn.f32x2 %0, %1, %2, %3;" : "=l"(d) : "l"(a), "l"(b), "l"(c));
    return d;
}
__device__ __forceinline__ float f2sum(u64 v) {
    return __uint_as_float((unsigned)v) + __uint_as_float((unsigned)(v >> 32));
}

// ---------------------------------------------------------------------------
// QKV GEMM with fused input prep. Block: 32 rows x 192 cols, 256 threads,
// 4x6 output tile per thread, packed f32x2 math. Grid (2, 63) = 126 blocks
// -> exactly one block per SM (single wave). Smem: As 16KB + Ws 99KB.
// ---------------------------------------------------------------------------
__global__ __launch_bounds__(256) void qkv_gemm_kernel(
    const float* __restrict__ x, const float* __restrict__ coords9,
    const float* __restrict__ prompt,
    const float* __restrict__ pe_w, const float* __restrict__ pe_b,
    const float* __restrict__ pe_g, const float* __restrict__ pe_bt,
    const float* __restrict__ W, const float* __restrict__ bias, int n)
{
    extern __shared__ float smem[];
    float* As = smem;                 // 32*128
    float* Ws = smem + 32*128;        // 192*132 (padded rows)

    int row0 = blockIdx.y * 32;
    int col0 = blockIdx.x * 192;
    int tid  = threadIdx.x;
    int w    = tid >> 5;
    int lane = tid & 31;

    // ---- load W tile: 192 cols x 128 k ----
    #pragma unroll
    for (int u = 0; u < 24; u++) {
        int lin = tid + u*256;
        int cc = lin >> 5, k4 = lin & 31;
        float4 wv = ((const float4*)(W + (size_t)(col0 + cc)*128))[k4];
        ((float4*)(Ws + cc*132))[k4] = wv;
    }

    // ---- fused prep: warp w computes rows w*4 .. w*4+3 ----
    #pragma unroll 1
    for (int u = 0; u < 4; u++) {
        int r = w*4 + u;
        int i = row0 + r;
        if (i >= n) {
            As[r*128 + lane] = 0.f; As[r*128 + 32 + lane] = 0.f;
            As[r*128 + 64 + lane] = 0.f; As[r*128 + 96 + lane] = 0.f;
            continue;
        }
        float cv = (lane < 9) ? coords9[i*9 + lane] : 0.f;
        const float inv3 = 1.0f / 3.0f;
        float cx = (__shfl_sync(0xffffffffu, cv, 0) + __shfl_sync(0xffffffffu, cv, 3) + __shfl_sync(0xffffffffu, cv, 6)) * inv3;
        float cy = (__shfl_sync(0xffffffffu, cv, 1) + __shfl_sync(0xffffffffu, cv, 4) + __shfl_sync(0xffffffffu, cv, 7)) * inv3;
        float cz = (__shfl_sync(0xffffffffu, cv, 2) + __shfl_sync(0xffffffffu, cv, 5) + __shfl_sync(0xffffffffu, cv, 8)) * inv3;
        if (col0 == 0 && lane == 0) g_cent[i] = make_float4(cx, cy, cz, 0.f);

        float v = cx*pe_w[lane] + cy*pe_w[32+lane] + cz*pe_w[64+lane] + pe_b[lane];
        float h = 0.5f * v * (1.0f + erff(v * 0.70710678118654752f));

        float s = h, s2 = h*h;
        #pragma unroll
        for (int off = 16; off; off >>= 1) {
            s  += __shfl_xor_sync(0xffffffffu, s,  off);
            s2 += __shfl_xor_sync(0xffffffffu, s2, off);
        }
        float mu  = s * (1.0f/32.0f);
        float var = s2 * (1.0f/32.0f) - mu*mu;
        float inv = rsqrtf(var + 1e-5f);

        As[r*128 +      lane] = x[i*EMB +      lane] + prompt[     lane];
        As[r*128 + 32 + lane] = x[i*EMB + 32 + lane] + prompt[32 + lane];
        As[r*128 + 64 + lane] = x[i*EMB + 64 + lane] + prompt[64 + lane];
        As[r*128 + 96 + lane] = (h - mu) * inv * pe_g[lane] + pe_bt[lane];
    }
    __syncthreads();

    // ---- compute: thread -> 4 rows x 6 cols, packed f32x2 ----
    int tx = tid & 31;
    int ty = tid >> 5;
    const ulonglong2* wp[6];
    #pragma unroll
    for (int c = 0; c < 6; c++) wp[c] = (const ulonglong2*)(Ws + (tx + 32*c)*132);
    const ulonglong2* ap[4];
    #pragma unroll
    for (int r = 0; r < 4; r++) ap[r] = (const ulonglong2*)(As + (ty*4 + r)*128);

    u64 acc[4][6];
    #pragma unroll
    for (int r = 0; r < 4; r++)
        #pragma unroll
        for (int c = 0; c < 6; c++) acc[r][c] = 0ULL;

    #pragma unroll 4
    for (int k4 = 0; k4 < 32; k4++) {
        ulonglong2 wv[6], av[4];
        #pragma unroll
        for (int c = 0; c < 6; c++) wv[c] = wp[c][k4];
        #pragma unroll
        for (int r = 0; r < 4; r++) av[r] = ap[r][k4];
        #pragma unroll
        for (int r = 0; r < 4; r++)
            #pragma unroll
            for (int c = 0; c < 6; c++) {
                acc[r][c] = ffma2(av[r].x, wv[c].x, acc[r][c]);
                acc[r][c] = ffma2(av[r].y, wv[c].y, acc[r][c]);
            }
    }

    float bv[6];
    #pragma unroll
    for (int c = 0; c < 6; c++) bv[c] = bias[col0 + tx + 32*c];
    #pragma unroll
    for (int r = 0; r < 4; r++) {
        int gr = row0 + ty*4 + r;
        if (gr < n) {
            #pragma unroll
            for (int c = 0; c < 6; c++)
                g_qkv[(size_t)gr*384 + col0 + tx + 32*c] = f2sum(acc[r][c]) + bv[c];
        }
    }
}

// ---------------------------------------------------------------------------
// Output GEMM: 16 rows x 128 cols per block, 256 threads, 2x4 tile, f32x2.
// Grid (1, 125) -> single wave. With sanitize.
// ---------------------------------------------------------------------------
__global__ __launch_bounds__(256) void out_gemm_kernel(
    const float* __restrict__ W, const float* __restrict__ bias,
    float* __restrict__ C, int n)
{
    extern __shared__ float smem[];
    float* As = smem;                 // 16*128
    float* Ws = smem + 16*128;        // 128*132

    int row0 = blockIdx.y * 16;
    int tid  = threadIdx.x;

    #pragma unroll
    for (int u = 0; u < 16; u++) {
        int lin = tid + u*256;
        int cc = lin >> 5, k4 = lin & 31;
        float4 wv = ((const float4*)(W + (size_t)cc*128))[k4];
        ((float4*)(Ws + cc*132))[k4] = wv;
    }
    #pragma unroll
    for (int u = 0; u < 2; u++) {
        int lin = tid + u*256;
        int r = lin >> 5, c4 = lin & 31;
        int gr = row0 + r;
        float4 av = make_float4(0.f,0.f,0.f,0.f);
        if (gr < n) av = ((const float4*)(g_o + (size_t)gr*128))[c4];
        ((float4*)(As + r*128))[c4] = av;
    }
    __syncthreads();

    int tx = tid & 31;
    int ty = tid >> 5;
    const ulonglong2* wp[4];
    #pragma unroll
    for (int c = 0; c < 4; c++) wp[c] = (const ulonglong2*)(Ws + (tx + 32*c)*132);
    const ulonglong2* ap[2];
    #pragma unroll
    for (int r = 0; r < 2; r++) ap[r] = (const ulonglong2*)(As + (ty*2 + r)*128);

    u64 acc[2][4];
    #pragma unroll
    for (int r = 0; r < 2; r++)
        #pragma unroll
        for (int c = 0; c < 4; c++) acc[r][c] = 0ULL;

    #pragma unroll 4
    for (int k4 = 0; k4 < 32; k4++) {
        ulonglong2 wv[4], av[2];
        #pragma unroll
        for (int c = 0; c < 4; c++) wv[c] = wp[c][k4];
        #pragma unroll
        for (int r = 0; r < 2; r++) av[r] = ap[r][k4];
        #pragma unroll
        for (int r = 0; r < 2; r++)
            #pragma unroll
            for (int c = 0; c < 4; c++) {
                acc[r][c] = ffma2(av[r].x, wv[c].x, acc[r][c]);
                acc[r][c] = ffma2(av[r].y, wv[c].y, acc[r][c]);
            }
    }

    #pragma unroll
    for (int r = 0; r < 2; r++) {
        int gr = row0 + ty*2 + r;
        if (gr < n) {
            #pragma unroll
            for (int c = 0; c < 4; c++) {
                int col = tx + 32*c;
                float v = f2sum(acc[r][c]) + bias[col];
                if (isnan(v)) v = 0.f;
                v = fminf(fmaxf(v, -1e4f), 1e4f);
                C[(size_t)gr*EMB + col] = v;
            }
        }
    }
}

// ---------------------------------------------------------------------------
// 2048-bin histogram select: finds bucket containing rank `rem` (1-indexed),
// writes bucket index and residual rank to shared outputs. Bins beyond the
// level's live range are zero and can never trigger. 256 threads, 8 bins each.
// ---------------------------------------------------------------------------
__device__ __forceinline__ void hist_select(
    const unsigned* hist, unsigned rem, unsigned* s_wpart,
    unsigned* out_bkt, unsigned* out_rem, int tid, int w, int lane)
{
    unsigned h[8]; unsigned lsum = 0u;
    #pragma unroll
    for (int u = 0; u < 8; u++) { h[u] = hist[tid*8 + u]; lsum += h[u]; }
    unsigned incl = lsum;
    #pragma unroll
    for (int off = 1; off < 32; off <<= 1) {
        unsigned v = __shfl_up_sync(0xffffffffu, incl, off);
        if (lane >= off) incl += v;
    }
    if (lane == 31) s_wpart[w] = incl;
    __syncthreads();
    unsigned wbase = 0u;
    #pragma unroll
    for (int u = 0; u < 8; u++) wbase += (u < w) ? s_wpart[u] : 0u;
    unsigned cum = wbase + incl - lsum;
    #pragma unroll
    for (int u = 0; u < 8; u++) {
        if (cum < rem && cum + h[u] >= rem) { *out_bkt = tid*8 + u; *out_rem = rem - cum; }
        cum += h[u];
    }
    __syncthreads();
}

// ---------------------------------------------------------------------------
// Fused top-K + sparse attention. One block (256 threads) per node.
// 11/11/10-bit radix select (all bins < 2048; pad key -> bin 2047) ->
// neighbor set -> head-per-warp attention. Ties at the rank-32 boundary take
// lowest indices (matches jax); within-set order irrelevant (mask is a set).
// ---------------------------------------------------------------------------
__global__ __launch_bounds__(256) void fused_attn_kernel(int n)
{
    __shared__ unsigned s_key[NMAX];          // 8 KB (fallback tie scan only)
    __shared__ unsigned s_hist[2048];         // 8 KB
    __shared__ float    s_p[NHEAD][KNBR];     // 1 KB
    __shared__ float    s_part[NHEAD][EMB];   // 4 KB
    __shared__ int      s_nbr[KNBR];
    __shared__ int      s_tie[64];
    __shared__ unsigned s_wpart[8];
    __shared__ unsigned s_b0, s_r0, s_b1, s_r1, s_b2, s_r2;
    __shared__ int      s_cnt, s_tcnt;

    int i    = blockIdx.x;
    int tid  = threadIdx.x;
    int w    = tid >> 5;
    int lane = tid & 31;

    // ---- zero hist, init counters ----
    #pragma unroll
    for (int u = 0; u < 8; u++) s_hist[tid + u*256] = 0u;
    if (tid == 0) { s_cnt = 0; s_tcnt = 0; }
    __syncthreads();

    // ---- gen pass: keys (registers) + level-0 histogram (top 11 bits) ----
    float4 c0 = g_cent[i];
    unsigned kreg[NMAX/256];
    #pragma unroll
    for (int u = 0; u < NMAX/256; u++) {
        int j = tid + u*256;
        unsigned k = 0xFFFFFFFFu;   // pad: bin 2047, above all finite keys
        if (j < n) {
            float4 cj = g_cent[j];
            float dx = cj.x - c0.x, dy = cj.y - c0.y, dz = cj.z - c0.z;
            k = __float_as_uint(dx*dx + dy*dy + dz*dz);
        }
        kreg[u] = k;
        s_key[j] = k;
        atomicAdd(&s_hist[k >> 21], 1u);
    }
    __syncthreads();

    // ---- level 0 select ----
    hist_select(s_hist, KNBR, s_wpart, &s_b0, &s_r0, tid, w, lane);
    unsigned b0 = s_b0, r0 = s_r0;

    // ---- rescan 1: middle 11 bits of keys with top bits == b0 ----
    #pragma unroll
    for (int u = 0; u < 8; u++) s_hist[tid + u*256] = 0u;
    __syncthreads();
    #pragma unroll
    for (int u = 0; u < NMAX/256; u++)
        if ((kreg[u] >> 21) == b0)
            atomicAdd(&s_hist[(kreg[u] >> 10) & 0x7FFu], 1u);
    __syncthreads();

    hist_select(s_hist, r0, s_wpart, &s_b1, &s_r1, tid, w, lane);
    unsigned pref21 = (b0 << 11) | s_b1;   // top 21 bits of T
    unsigned r1 = s_r1;

    // ---- rescan 2: low 10 bits of keys with top 21 bits == pref21 ----
    #pragma unroll
    for (int u = 0; u < 8; u++) s_hist[tid + u*256] = 0u;
    __syncthreads();
    #pragma unroll
    for (int u = 0; u < NMAX/256; u++)
        if ((kreg[u] >> 10) == pref21)
            atomicAdd(&s_hist[kreg[u] & 0x3FFu], 1u);
    __syncthreads();

    hist_select(s_hist, r1, s_wpart, &s_b2, &s_r2, tid, w, lane);
    unsigned T = (pref21 << 10) | s_b2;    // exact rank-32 key
    int need = (int)s_r2;                  // # of keys == T to take

    // ---- emission: keys < T direct; keys == T into tie buffer ----
    #pragma unroll
    for (int u = 0; u < NMAX/256; u++) {
        unsigned k = kreg[u];
        if (k < T) {
            int p = atomicAdd(&s_cnt, 1);
            s_nbr[p] = tid + u*256;
        } else if (k == T) {
            int p = atomicAdd(&s_tcnt, 1);
            if (p < 64) s_tie[p] = tid + u*256;
        }
    }
    __syncthreads();

    if (tid < 32) {
        int base = s_cnt;
        int t = s_tcnt;
        if (t <= 64) {
            // select `need` smallest indices from tie buffer (typically t=need=1)
            int v0 = (lane < t)      ? s_tie[lane]      : 0x7fffffff;
            int v1 = (lane + 32 < t) ? s_tie[lane + 32] : 0x7fffffff;
            #pragma unroll 1
            for (int it = 0; it < need; it++) {
                int mn = min(v0, v1);
                #pragma unroll
                for (int off = 16; off; off >>= 1)
                    mn = min(mn, __shfl_xor_sync(0xffffffffu, mn, off));
                if (v0 == mn) v0 = 0x7fffffff;
                else if (v1 == mn) v1 = 0x7fffffff;
                if (lane == 0) s_nbr[base + it] = mn;
            }
        } else {
            // degenerate fallback: ordered ballot scan over all keys
            int need2 = need; int pos = base;
            #pragma unroll 1
            for (int u = 0; u < NMAX/32 && need2 > 0; u++) {
                int j = u*32 + lane;
                unsigned k = s_key[j];
                unsigned beq = __ballot_sync(0xffffffffu, k == T);
                if (beq) {
                    int neq  = __popc(beq);
                    int take = need2 < neq ? need2 : neq;
                    if (k == T) {
                        int rank = __popc(beq & ((1u << lane) - 1u));
                        if (rank < take) s_nbr[pos + rank] = j;
                    }
                    pos  += take;
                    need2 -= take;
                }
            }
        }
    }
    __syncthreads();

    // ---- attention (head-per-warp) ----
    int idx_l = s_nbr[lane];
    int vrow[4];
    #pragma unroll
    for (int u = 0; u < 4; u++) vrow[u] = s_nbr[w*4 + u];

    float4 vreg[4];
    #pragma unroll
    for (int u = 0; u < 4; u++)
        vreg[u] = ((const float4*)(g_qkv + (size_t)vrow[u]*384 + 256))[lane];

    {
        const float4* kp = (const float4*)(g_qkv + (size_t)idx_l*384 + 128 + w*DHEAD);
        const float4* qp = (const float4*)(g_qkv + (size_t)i*384 + w*DHEAD);
        float4 q0 = qp[0], q1 = qp[1], q2 = qp[2], q3 = qp[3];
        float4 k0 = kp[0], k1 = kp[1], k2 = kp[2], k3 = kp[3];
        float s = dot4(q0,k0) + dot4(q1,k1) + dot4(q2,k2) + dot4(q3,k3);
        s *= 0.25f;   // 1/sqrt(16)

        float m = s;
        #pragma unroll
        for (int off = 16; off; off >>= 1)
            m = fmaxf(m, __shfl_xor_sync(0xffffffffu, m, off));
        float p = expf(s - m);
        float den = p;
        #pragma unroll
        for (int off = 16; off; off >>= 1)
            den += __shfl_xor_sync(0xffffffffu, den, off);
        s_p[w][lane] = p / den;
    }
    __syncthreads();

    {
        int hh = lane >> 2;
        float4 acc = make_float4(0.f,0.f,0.f,0.f);
        #pragma unroll
        for (int u = 0; u < 4; u++) {
            float p = s_p[hh][w*4 + u];
            acc.x += p * vreg[u].x;
            acc.y += p * vreg[u].y;
            acc.z += p * vreg[u].z;
            acc.w += p * vreg[u].w;
        }
        ((float4*)s_part[w])[lane] = acc;
    }
    __syncthreads();

    if (tid < 128) {
        float o = 0.f;
        #pragma unroll
        for (int ww = 0; ww < NHEAD; ww++) o += s_part[ww][tid];
        g_o[(size_t)i*EMB + tid] = o;
    }
}

// ---------------------------------------------------------------------------
extern "C" void kernel_launch(void* const* d_in, const int* in_sizes, int n_in,
                              void* d_out, int out_size)
{
    const float* x       = (const float*)d_in[0];
    const float* coords9 = (const float*)d_in[1];
    const float* prompt  = (const float*)d_in[2];
    const float* pe_w    = (const float*)d_in[3];
    const float* pe_b    = (const float*)d_in[4];
    const float* pe_g    = (const float*)d_in[5];
    const float* pe_bt   = (const float*)d_in[6];
    const float* in_w    = (const float*)d_in[7];
    const float* in_b    = (const float*)d_in[8];
    const float* out_w   = (const float*)d_in[9];
    const float* out_b   = (const float*)d_in[10];
    float* out = (float*)d_out;

    int n = in_sizes[0] / EMB;     // 2000
    int nrb32 = (n + 31) / 32;     // 63
    int nrb16 = (n + 15) / 16;     // 125

    const int QKV_SMEM = (32*128 + 192*132) * (int)sizeof(float);   // 117760 B
    const int OUT_SMEM = (16*128 + 128*132) * (int)sizeof(float);   // 75776 B
    cudaFuncSetAttribute(qkv_gemm_kernel, cudaFuncAttributeMaxDynamicSharedMemorySize, QKV_SMEM);
    cudaFuncSetAttribute(out_gemm_kernel, cudaFuncAttributeMaxDynamicSharedMemorySize, OUT_SMEM);

    qkv_gemm_kernel<<<dim3(2, nrb32), 256, QKV_SMEM>>>(
        x, coords9, prompt, pe_w, pe_b, pe_g, pe_bt, in_w, in_b, n);
    fused_attn_kernel<<<n, 256>>>(n);
    out_gemm_kernel<<<dim3(1, nrb16), 256, OUT_SMEM>>>(out_w, out_b, out, n);
}

// round 9
// speedup vs baseline: 1.1424x; 1.1424x over previous
#include <cuda_runtime.h>
#include <cuda_bf16.h>
#include <math.h>

#define EMB 128
#define NHEAD 8
#define DHEAD 16
#define KNBR 32
#define NMAX 2048

typedef unsigned long long u64;

// Scratch (no cudaMalloc allowed)
__device__ float4 g_cent[NMAX];
__device__ float  g_qkv [NMAX * 3 * EMB];
__device__ float  g_o   [NMAX * EMB];

__device__ __forceinline__ float dot4(float4 a, float4 b) {
    return a.x*b.x + a.y*b.y + a.z*b.z + a.w*b.w;
}

// Packed fp32 FMA: d.lo = a.lo*b.lo + c.lo ; d.hi = a.hi*b.hi + c.hi
__device__ __forceinline__ u64 ffma2(u64 a, u64 b, u64 c) {
    u64 d;
    asm("fma.rn.f32x2 %0, %1, %2, %3;" : "=l"(d) : "l"(a), "l"(b), "l"(c));
    return d;
}
__device__ __forceinline__ float f2sum(u64 v) {
    return __uint_as_float((unsigned)v) + __uint_as_float((unsigned)(v >> 32));
}

// ---------------------------------------------------------------------------
// QKV GEMM with fused input prep. Block: 32 rows x 192 cols, 256 threads,
// 4x6 output tile per thread, packed f32x2. Grid (2,63)=126 -> single wave.
// ---------------------------------------------------------------------------
__global__ __launch_bounds__(256) void qkv_gemm_kernel(
    const float* __restrict__ x, const float* __restrict__ coords9,
    const float* __restrict__ prompt,
    const float* __restrict__ pe_w, const float* __restrict__ pe_b,
    const float* __restrict__ pe_g, const float* __restrict__ pe_bt,
    const float* __restrict__ W, const float* __restrict__ bias, int n)
{
    extern __shared__ float smem[];
    float* As = smem;                 // 32*128
    float* Ws = smem + 32*128;        // 192*132 (padded rows)

    int row0 = blockIdx.y * 32;
    int col0 = blockIdx.x * 192;
    int tid  = threadIdx.x;
    int w    = tid >> 5;
    int lane = tid & 31;

    #pragma unroll
    for (int u = 0; u < 24; u++) {
        int lin = tid + u*256;
        int cc = lin >> 5, k4 = lin & 31;
        float4 wv = ((const float4*)(W + (size_t)(col0 + cc)*128))[k4];
        ((float4*)(Ws + cc*132))[k4] = wv;
    }

    // fused prep: warp w computes rows w*4 .. w*4+3
    #pragma unroll 1
    for (int u = 0; u < 4; u++) {
        int r = w*4 + u;
        int i = row0 + r;
        if (i >= n) {
            As[r*128 + lane] = 0.f; As[r*128 + 32 + lane] = 0.f;
            As[r*128 + 64 + lane] = 0.f; As[r*128 + 96 + lane] = 0.f;
            continue;
        }
        float cv = (lane < 9) ? coords9[i*9 + lane] : 0.f;
        const float inv3 = 1.0f / 3.0f;
        float cx = (__shfl_sync(0xffffffffu, cv, 0) + __shfl_sync(0xffffffffu, cv, 3) + __shfl_sync(0xffffffffu, cv, 6)) * inv3;
        float cy = (__shfl_sync(0xffffffffu, cv, 1) + __shfl_sync(0xffffffffu, cv, 4) + __shfl_sync(0xffffffffu, cv, 7)) * inv3;
        float cz = (__shfl_sync(0xffffffffu, cv, 2) + __shfl_sync(0xffffffffu, cv, 5) + __shfl_sync(0xffffffffu, cv, 8)) * inv3;
        if (col0 == 0 && lane == 0) g_cent[i] = make_float4(cx, cy, cz, 0.f);

        float v = cx*pe_w[lane] + cy*pe_w[32+lane] + cz*pe_w[64+lane] + pe_b[lane];
        float h = 0.5f * v * (1.0f + erff(v * 0.70710678118654752f));

        float s = h, s2 = h*h;
        #pragma unroll
        for (int off = 16; off; off >>= 1) {
            s  += __shfl_xor_sync(0xffffffffu, s,  off);
            s2 += __shfl_xor_sync(0xffffffffu, s2, off);
        }
        float mu  = s * (1.0f/32.0f);
        float var = s2 * (1.0f/32.0f) - mu*mu;
        float inv = rsqrtf(var + 1e-5f);

        As[r*128 +      lane] = x[i*EMB +      lane] + prompt[     lane];
        As[r*128 + 32 + lane] = x[i*EMB + 32 + lane] + prompt[32 + lane];
        As[r*128 + 64 + lane] = x[i*EMB + 64 + lane] + prompt[64 + lane];
        As[r*128 + 96 + lane] = (h - mu) * inv * pe_g[lane] + pe_bt[lane];
    }
    __syncthreads();

    int tx = tid & 31;
    int ty = tid >> 5;
    const ulonglong2* wp[6];
    #pragma unroll
    for (int c = 0; c < 6; c++) wp[c] = (const ulonglong2*)(Ws + (tx + 32*c)*132);
    const ulonglong2* ap[4];
    #pragma unroll
    for (int r = 0; r < 4; r++) ap[r] = (const ulonglong2*)(As + (ty*4 + r)*128);

    u64 acc[4][6];
    #pragma unroll
    for (int r = 0; r < 4; r++)
        #pragma unroll
        for (int c = 0; c < 6; c++) acc[r][c] = 0ULL;

    #pragma unroll 4
    for (int k4 = 0; k4 < 32; k4++) {
        ulonglong2 wv[6], av[4];
        #pragma unroll
        for (int c = 0; c < 6; c++) wv[c] = wp[c][k4];
        #pragma unroll
        for (int r = 0; r < 4; r++) av[r] = ap[r][k4];
        #pragma unroll
        for (int r = 0; r < 4; r++)
            #pragma unroll
            for (int c = 0; c < 6; c++) {
                acc[r][c] = ffma2(av[r].x, wv[c].x, acc[r][c]);
                acc[r][c] = ffma2(av[r].y, wv[c].y, acc[r][c]);
            }
    }

    float bv[6];
    #pragma unroll
    for (int c = 0; c < 6; c++) bv[c] = bias[col0 + tx + 32*c];
    #pragma unroll
    for (int r = 0; r < 4; r++) {
        int gr = row0 + ty*4 + r;
        if (gr < n) {
            #pragma unroll
            for (int c = 0; c < 6; c++)
                g_qkv[(size_t)gr*384 + col0 + tx + 32*c] = f2sum(acc[r][c]) + bv[c];
        }
    }
}

// ---------------------------------------------------------------------------
// Output GEMM (round-6 proven config): 32 rows x 64 cols, 256 threads,
// 4x2 tile, float4. Grid (2,63)=126 -> single wave. With sanitize.
// ---------------------------------------------------------------------------
__global__ __launch_bounds__(256) void out_gemm_kernel(
    const float* __restrict__ W, const float* __restrict__ bias,
    float* __restrict__ C, int n)
{
    extern __shared__ float smem[];
    float* As = smem;                 // 32*128
    float* Ws = smem + 32*128;        // 64*132

    int row0 = blockIdx.y * 32;
    int col0 = blockIdx.x * 64;
    int tid  = threadIdx.x;

    #pragma unroll
    for (int u = 0; u < 8; u++) {
        int lin = tid + u*256;
        int cc = lin >> 5, k4 = lin & 31;
        float4 wv = ((const float4*)(W + (size_t)(col0 + cc)*128))[k4];
        ((float4*)(Ws + cc*132))[k4] = wv;
    }
    #pragma unroll
    for (int u = 0; u < 4; u++) {
        int lin = tid + u*256;
        int r = lin >> 5, c4 = lin & 31;
        int gr = row0 + r;
        float4 av = make_float4(0.f,0.f,0.f,0.f);
        if (gr < n) av = ((const float4*)(g_o + (size_t)gr*128))[c4];
        ((float4*)(As + r*128))[c4] = av;
    }
    __syncthreads();

    int tx = tid & 31;
    int ty = tid >> 5;
    const float4* w0p = (const float4*)(Ws + tx*132);
    const float4* w1p = (const float4*)(Ws + (tx+32)*132);

    float acc[4][2] = {{0.f,0.f},{0.f,0.f},{0.f,0.f},{0.f,0.f}};
    #pragma unroll
    for (int k4 = 0; k4 < 32; k4++) {
        float4 w0 = w0p[k4], w1 = w1p[k4];
        #pragma unroll
        for (int r = 0; r < 4; r++) {
            float4 a = ((const float4*)(As + (ty*4+r)*128))[k4];
            acc[r][0] += dot4(a, w0);
            acc[r][1] += dot4(a, w1);
        }
    }

    int c0 = col0 + tx, c1 = col0 + tx + 32;
    float b0 = bias[c0], b1 = bias[c1];
    #pragma unroll
    for (int r = 0; r < 4; r++) {
        int gr = row0 + ty*4 + r;
        if (gr < n) {
            float v0 = acc[r][0] + b0;
            float v1 = acc[r][1] + b1;
            if (isnan(v0)) v0 = 0.f;
            if (isnan(v1)) v1 = 0.f;
            v0 = fminf(fmaxf(v0, -1e4f), 1e4f);
            v1 = fminf(fmaxf(v1, -1e4f), 1e4f);
            C[(size_t)gr*EMB + c0] = v0;
            C[(size_t)gr*EMB + c1] = v1;
        }
    }
}

// ---------------------------------------------------------------------------
// Fused top-K + sparse attention (round-6 structure: 256-bin 4-level radix,
// register keys) + warp-aggregated histogram atomics (top byte = exponent,
// heavily repeated within warps) + tie-buffer fast path for boundary keys.
// Ties at rank-32 take lowest indices (matches jax); set order irrelevant.
// ---------------------------------------------------------------------------
__global__ __launch_bounds__(256) void fused_attn_kernel(int n)
{
    __shared__ unsigned s_key[NMAX];          // 8 KB (fallback tie scan only)
    __shared__ unsigned s_hist[256];          // 1 KB
    __shared__ float    s_p[NHEAD][KNBR];     // 1 KB
    __shared__ float    s_part[NHEAD][EMB];   // 4 KB
    __shared__ int      s_nbr[KNBR];
    __shared__ int      s_tie[64];
    __shared__ unsigned s_Tkey, s_rem;
    __shared__ int      s_cnt, s_tcnt;

    int i    = blockIdx.x;
    int tid  = threadIdx.x;
    int w    = tid >> 5;
    int lane = tid & 31;

    s_hist[tid] = 0u;
    if (tid == 0) { s_Tkey = 0u; s_rem = KNBR; s_cnt = 0; s_tcnt = 0; }
    __syncthreads();

    // ---- gen pass: keys (registers) + level-0 histogram, warp-aggregated ----
    float4 c0 = g_cent[i];
    unsigned kreg[NMAX/256];
    #pragma unroll
    for (int u = 0; u < NMAX/256; u++) {
        int j = tid + u*256;
        unsigned k = 0xFFFFFFFFu;   // pad: bin 255, above all finite keys
        if (j < n) {
            float4 cj = g_cent[j];
            float dx = cj.x - c0.x, dy = cj.y - c0.y, dz = cj.z - c0.z;
            k = __float_as_uint(dx*dx + dy*dy + dz*dz);
        }
        kreg[u] = k;
        s_key[j] = k;
        int b = k >> 24;   // sign+exponent byte: few distinct values per warp
        unsigned grp = __match_any_sync(0xffffffffu, b);
        if ((grp & ((1u << lane) - 1u)) == 0u)      // group leader
            atomicAdd(&s_hist[b], (unsigned)__popc(grp));
    }
    __syncthreads();

    // ---- radix descent: 4 levels of 8 bits -------------------------------
    #pragma unroll 1
    for (int level = 0; level < 4; level++) {
        int shift = 24 - level*8;

        if (tid < 32) {   // warp 0 scans 256 bins (8 per lane)
            unsigned h[8]; unsigned lsum = 0u;
            #pragma unroll
            for (int u = 0; u < 8; u++) { h[u] = s_hist[lane*8 + u]; lsum += h[u]; }
            unsigned incl = lsum;
            #pragma unroll
            for (int off = 1; off < 32; off <<= 1) {
                unsigned v = __shfl_up_sync(0xffffffffu, incl, off);
                if (lane >= off) incl += v;
            }
            unsigned cum = incl - lsum;
            unsigned rem = s_rem;
            int bloc = -1; unsigned cb_loc = 0u;
            #pragma unroll
            for (int u = 0; u < 8; u++) {
                if (cum < rem && cum + h[u] >= rem) { bloc = lane*8 + u; cb_loc = cum; }
                cum += h[u];
            }
            unsigned bal = __ballot_sync(0xffffffffu, bloc >= 0);
            int src = __ffs(bal) - 1;
            if (lane == src) {
                s_Tkey |= ((unsigned)bloc) << shift;
                s_rem   = rem - cb_loc;
            }
        }
        __syncthreads();

        if (level < 3) {
            unsigned pref = s_Tkey >> shift;
            s_hist[tid] = 0u;
            __syncthreads();
            #pragma unroll
            for (int u = 0; u < NMAX/256; u++) {
                unsigned k = kreg[u];
                if ((k >> shift) == pref)
                    atomicAdd(&s_hist[(k >> (shift - 8)) & 0xFFu], 1u);
            }
            __syncthreads();
        }
    }

    // ---- emission: keys < T direct; keys == T into tie buffer ----
    unsigned T = s_Tkey;
    int need = (int)s_rem;
    #pragma unroll
    for (int u = 0; u < NMAX/256; u++) {
        unsigned k = kreg[u];
        if (k < T) {
            int p = atomicAdd(&s_cnt, 1);
            s_nbr[p] = tid + u*256;
        } else if (k == T) {
            int p = atomicAdd(&s_tcnt, 1);
            if (p < 64) s_tie[p] = tid + u*256;
        }
    }
    __syncthreads();

    if (tid < 32) {
        int base = s_cnt;
        int t = s_tcnt;
        if (t <= 64) {
            // select `need` smallest tie indices (typically t=need=1)
            int v0 = (lane < t)      ? s_tie[lane]      : 0x7fffffff;
            int v1 = (lane + 32 < t) ? s_tie[lane + 32] : 0x7fffffff;
            #pragma unroll 1
            for (int it = 0; it < need; it++) {
                int mn = min(v0, v1);
                #pragma unroll
                for (int off = 16; off; off >>= 1)
                    mn = min(mn, __shfl_xor_sync(0xffffffffu, mn, off));
                if (v0 == mn) v0 = 0x7fffffff;
                else if (v1 == mn) v1 = 0x7fffffff;
                if (lane == 0) s_nbr[base + it] = mn;
            }
        } else {
            // degenerate fallback: ordered ballot scan over all keys
            int need2 = need; int pos = base;
            #pragma unroll 1
            for (int u = 0; u < NMAX/32 && need2 > 0; u++) {
                int j = u*32 + lane;
                unsigned k = s_key[j];
                unsigned beq = __ballot_sync(0xffffffffu, k == T);
                if (beq) {
                    int neq  = __popc(beq);
                    int take = need2 < neq ? need2 : neq;
                    if (k == T) {
                        int rank = __popc(beq & ((1u << lane) - 1u));
                        if (rank < take) s_nbr[pos + rank] = j;
                    }
                    pos  += take;
                    need2 -= take;
                }
            }
        }
    }
    __syncthreads();

    // ---- attention (head-per-warp) ----
    int idx_l = s_nbr[lane];
    int vrow[4];
    #pragma unroll
    for (int u = 0; u < 4; u++) vrow[u] = s_nbr[w*4 + u];

    float4 vreg[4];
    #pragma unroll
    for (int u = 0; u < 4; u++)
        vreg[u] = ((const float4*)(g_qkv + (size_t)vrow[u]*384 + 256))[lane];

    {
        const float4* kp = (const float4*)(g_qkv + (size_t)idx_l*384 + 128 + w*DHEAD);
        const float4* qp = (const float4*)(g_qkv + (size_t)i*384 + w*DHEAD);
        float4 q0 = qp[0], q1 = qp[1], q2 = qp[2], q3 = qp[3];
        float4 k0 = kp[0], k1 = kp[1], k2 = kp[2], k3 = kp[3];
        float s = dot4(q0,k0) + dot4(q1,k1) + dot4(q2,k2) + dot4(q3,k3);
        s *= 0.25f;   // 1/sqrt(16)

        float m = s;
        #pragma unroll
        for (int off = 16; off; off >>= 1)
            m = fmaxf(m, __shfl_xor_sync(0xffffffffu, m, off));
        float p = expf(s - m);
        float den = p;
        #pragma unroll
        for (int off = 16; off; off >>= 1)
            den += __shfl_xor_sync(0xffffffffu, den, off);
        s_p[w][lane] = p / den;
    }
    __syncthreads();

    {
        int hh = lane >> 2;
        float4 acc = make_float4(0.f,0.f,0.f,0.f);
        #pragma unroll
        for (int u = 0; u < 4; u++) {
            float p = s_p[hh][w*4 + u];
            acc.x += p * vreg[u].x;
            acc.y += p * vreg[u].y;
            acc.z += p * vreg[u].z;
            acc.w += p * vreg[u].w;
        }
        ((float4*)s_part[w])[lane] = acc;
    }
    __syncthreads();

    if (tid < 128) {
        float o = 0.f;
        #pragma unroll
        for (int ww = 0; ww < NHEAD; ww++) o += s_part[ww][tid];
        g_o[(size_t)i*EMB + tid] = o;
    }
}

// ---------------------------------------------------------------------------
extern "C" void kernel_launch(void* const* d_in, const int* in_sizes, int n_in,
                              void* d_out, int out_size)
{
    const float* x       = (const float*)d_in[0];
    const float* coords9 = (const float*)d_in[1];
    const float* prompt  = (const float*)d_in[2];
    const float* pe_w    = (const float*)d_in[3];
    const float* pe_b    = (const float*)d_in[4];
    const float* pe_g    = (const float*)d_in[5];
    const float* pe_bt   = (const float*)d_in[6];
    const float* in_w    = (const float*)d_in[7];
    const float* in_b    = (const float*)d_in[8];
    const float* out_w   = (const float*)d_in[9];
    const float* out_b   = (const float*)d_in[10];
    float* out = (float*)d_out;

    int n = in_sizes[0] / EMB;     // 2000
    int nrb = (n + 31) / 32;       // 63

    const int QKV_SMEM = (32*128 + 192*132) * (int)sizeof(float);   // 117760 B
    const int OUT_SMEM = (32*128 +  64*132) * (int)sizeof(float);   // 50176 B
    cudaFuncSetAttribute(qkv_gemm_kernel, cudaFuncAttributeMaxDynamicSharedMemorySize, QKV_SMEM);
    cudaFuncSetAttribute(out_gemm_kernel, cudaFuncAttributeMaxDynamicSharedMemorySize, OUT_SMEM);

    qkv_gemm_kernel<<<dim3(2, nrb), 256, QKV_SMEM>>>(
        x, coords9, prompt, pe_w, pe_b, pe_g, pe_bt, in_w, in_b, n);
    fused_attn_kernel<<<n, 256>>>(n);
    out_gemm_kernel<<<dim3(2, nrb), 256, OUT_SMEM>>>(out_w, out_b, out, n);
}